// round 6
// baseline (speedup 1.0000x reference)
#include <cuda_runtime.h>
#include <cstdint>

// ============================================================================
// out = dequant( fp8(x*xs) @ fp8(w^T*ws)^T ) * (1/xs)(1/ws)
//   x: [8,8192,512] f32 -> M=65536, K=512 ; w: [512,512] f32 -> N=512
// 4 launches:
//   1. init            (zero amax accumulators)
//   2. amax_all        (x blocks + w blocks, atomicMax on float bits)
//   3. quant_w         (w^T -> e4m3 pre-swizzled B SMEM images, scale inline)
//   4. fused GEMM      (quantize A slice into smem once, loop 4 B tiles,
//                       mma.sync m16n8k32 e4m3, dequant epilogue)
// NOTE: tcgen05/TMEM is unusable here — the harness lowers through plain
// compute_103 PTX and ptxas rejects all 'a'-gated instructions.
// ============================================================================

#define KDIM 512
#define NDIM 512
#define MDIM 65536
#define BM 64
#define BN 128
#define GEMM_THREADS 256
#define X_AMAX_BLOCKS 2048
#define W_AMAX_BLOCKS 8

#define SMEM_A_OFF 0
#define SMEM_A_BYTES (BM * KDIM)                  // 32768
#define SMEM_B_OFF SMEM_A_BYTES
#define SMEM_B_BYTES (BN * KDIM)                  // 65536
#define SMEM_TOTAL (SMEM_A_BYTES + SMEM_B_BYTES)  // 98304

// ---------------------------------------------------------------------------
// device globals
// ---------------------------------------------------------------------------
__device__ unsigned int g_amax_x_bits;
__device__ unsigned int g_amax_w_bits;
// B image: per n-block (128 rows): offset = nb*65536 + r*512 + swz(g,r), r=n%128
__device__ unsigned char g_wq[NDIM * KDIM];

// ---------------------------------------------------------------------------
// helpers
// ---------------------------------------------------------------------------
__device__ __forceinline__ uint32_t smem_u32(const void* p) {
    uint32_t a;
    asm("{ .reg .u64 t; cvta.to.shared.u64 t, %1; cvt.u32.u64 %0, t; }"
        : "=r"(a) : "l"(p));
    return a;
}

// 16B-granule swizzle within a 512B row: granule g of row r -> ((g^(r&7))<<4).
// Conflict-free for ldmatrix 8-row groups and full-row STS.128.
__device__ __forceinline__ uint32_t swz(uint32_t g, uint32_t r) {
    return (g ^ (r & 7u)) << 4;
}

// IEEE-exact scale computation (identical formula in every consumer)
__device__ __forceinline__ float x_scale_inline() {
    return __fdiv_rn(448.0f, fmaxf(__uint_as_float(g_amax_x_bits), 1e-12f));
}
__device__ __forceinline__ float w_scale_inline() {
    return __fdiv_rn(448.0f, fmaxf(__uint_as_float(g_amax_w_bits), 1e-12f));
}

// pack two floats -> two e4m3 bytes (RN + saturate == reference clip+cast)
__device__ __forceinline__ uint32_t f2e4m3x2(float lo, float hi) {
    unsigned short v;
    asm("cvt.rn.satfinite.e4m3x2.f32 %0, %1, %2;" : "=h"(v) : "f"(hi), "f"(lo));
    return (uint32_t)v;
}

__device__ __forceinline__ unsigned char f2e4m3_one(float f) {
    unsigned short v;
    asm("cvt.rn.satfinite.e4m3x2.f32 %0, %1, %2;" : "=h"(v) : "f"(0.0f), "f"(f));
    return (unsigned char)(v & 0xFF);
}

__device__ __forceinline__ void ldsm_x4(uint32_t* r, uint32_t addr) {
    asm volatile(
        "ldmatrix.sync.aligned.m8n8.x4.shared.b16 {%0,%1,%2,%3}, [%4];"
        : "=r"(r[0]), "=r"(r[1]), "=r"(r[2]), "=r"(r[3]) : "r"(addr));
}

__device__ __forceinline__ void mma_e4m3(float* d, const uint32_t* a,
                                         uint32_t b0, uint32_t b1) {
    asm volatile(
        "mma.sync.aligned.m16n8k32.row.col.f32.e4m3.e4m3.f32 "
        "{%0,%1,%2,%3}, {%4,%5,%6,%7}, {%8,%9}, {%0,%1,%2,%3};"
        : "+f"(d[0]), "+f"(d[1]), "+f"(d[2]), "+f"(d[3])
        : "r"(a[0]), "r"(a[1]), "r"(a[2]), "r"(a[3]), "r"(b0), "r"(b1));
}

// ---------------------------------------------------------------------------
// kernel 1: reset amax accumulators
// ---------------------------------------------------------------------------
__global__ void init_kernel() {
    g_amax_x_bits = 0u;
    g_amax_w_bits = 0u;
}

// ---------------------------------------------------------------------------
// kernel 2: fused grid-stride |max| over x (blocks < X_AMAX_BLOCKS) and w
// (nonneg floats: bit-max == float-max, so atomicMax on uint bits is exact)
// ---------------------------------------------------------------------------
__global__ void amax_all_kernel(const float4* __restrict__ x4,
                                const float4* __restrict__ w4) {
    const bool is_w = blockIdx.x >= X_AMAX_BLOCKS;
    const float4* p = is_w ? w4 : x4;
    const int n4 = is_w ? (KDIM * NDIM) / 4 : (MDIM * KDIM) / 4;
    const int bid = is_w ? (blockIdx.x - X_AMAX_BLOCKS) : blockIdx.x;
    const int nblk = is_w ? W_AMAX_BLOCKS : X_AMAX_BLOCKS;

    float m = 0.0f;
    for (int i = bid * blockDim.x + threadIdx.x; i < n4; i += nblk * blockDim.x) {
        float4 v = p[i];
        m = fmaxf(m, fmaxf(fmaxf(fabsf(v.x), fabsf(v.y)),
                           fmaxf(fabsf(v.z), fabsf(v.w))));
    }
    #pragma unroll
    for (int o = 16; o; o >>= 1) m = fmaxf(m, __shfl_xor_sync(0xffffffffu, m, o));
    __shared__ float wmax[8];
    int wid = threadIdx.x >> 5;
    if ((threadIdx.x & 31) == 0) wmax[wid] = m;
    __syncthreads();
    if (threadIdx.x < 8) {
        float mm = wmax[threadIdx.x];
        #pragma unroll
        for (int o = 4; o; o >>= 1) mm = fmaxf(mm, __shfl_xor_sync(0xffu, mm, o));
        if (threadIdx.x == 0) {
            atomicMax(is_w ? &g_amax_w_bits : &g_amax_x_bits,
                      __float_as_uint(mm));
        }
    }
}

// ---------------------------------------------------------------------------
// kernel 3: quantize weight transposed into pre-swizzled B SMEM images
// ---------------------------------------------------------------------------
__global__ void quant_w_kernel(const float* __restrict__ w) {
    int idx = blockIdx.x * blockDim.x + threadIdx.x;  // k*512 + n
    float ws = w_scale_inline();
    int k = idx >> 9;
    int n = idx & 511;
    unsigned char b = f2e4m3_one(w[idx] * ws);
    uint32_t r = (uint32_t)(n & 127);
    uint32_t off = (uint32_t)(n >> 7) * 65536u + r * 512u +
                   swz((uint32_t)k >> 4, r) + (uint32_t)(k & 15);
    g_wq[off] = b;
}

// ---------------------------------------------------------------------------
// kernel 4: fused quantize-A + FP8 GEMM, CTA = 64-row m-tile x full N.
// Quantize x slice once into swizzled smem A image, then loop 4 B tiles
// (64KB each, L2-resident). 8 warps, warp tile 32x32, 16 K-steps of 32.
// ---------------------------------------------------------------------------
__global__ void __launch_bounds__(GEMM_THREADS, 2)
fp8_gemm_kernel(const float* __restrict__ x, float* __restrict__ out) {
    extern __shared__ char smem[];
    const uint32_t sb = smem_u32(smem);
    const int tid = threadIdx.x;
    const int lid = tid & 31;
    const int wid = tid >> 5;
    const int wm = wid & 1;   // 2 m-subtiles of 32
    const int wn = wid >> 1;  // 4 n-subtiles of 32
    const int mt = blockIdx.x;  // m-tile (64 rows)

    // ---- quantize this CTA's A slice: 64 rows x 512 -> swizzled smem image
    const float xs = x_scale_inline();
    #pragma unroll
    for (int i = 0; i < 8; i++) {
        int g = tid + i * GEMM_THREADS;  // 0..2047 granules of 16 fp8 bytes
        int r = g >> 5;                  // row in tile
        int gc = g & 31;                 // granule within row
        const float4* p = reinterpret_cast<const float4*>(
            x + (size_t)(mt * BM + r) * KDIM + gc * 16);
        float4 f0 = p[0], f1 = p[1], f2 = p[2], f3 = p[3];
        uint4 q;
        q.x = f2e4m3x2(f0.x * xs, f0.y * xs) | (f2e4m3x2(f0.z * xs, f0.w * xs) << 16);
        q.y = f2e4m3x2(f1.x * xs, f1.y * xs) | (f2e4m3x2(f1.z * xs, f1.w * xs) << 16);
        q.z = f2e4m3x2(f2.x * xs, f2.y * xs) | (f2e4m3x2(f2.z * xs, f2.w * xs) << 16);
        q.w = f2e4m3x2(f3.x * xs, f3.y * xs) | (f2e4m3x2(f3.z * xs, f3.w * xs) << 16);
        *reinterpret_cast<uint4*>(smem + SMEM_A_OFF + r * 512 +
                                  swz((uint32_t)gc, (uint32_t)r)) = q;
    }

    // ---- per-lane ldmatrix addressing (layouts identical to B image builder)
    const uint32_t arow = (uint32_t)(wm * 32 + (lid & 15));
    const uint32_t ahalf = (uint32_t)(lid >> 4);
    const uint32_t abase = sb + SMEM_A_OFF + arow * 512u;
    const uint32_t brow = (uint32_t)(wn * 32 + (lid & 7) + ((lid & 16) >> 1));
    const uint32_t bhalf = (uint32_t)((lid >> 3) & 1);
    const uint32_t bbase = sb + SMEM_B_OFF + brow * 512u;
    const uint32_t lxor = (uint32_t)(lid & 7);

    const float ws = w_scale_inline();
    const float inv = __fmul_rn(__frcp_rn(xs), __frcp_rn(ws));
    const int qr = lid >> 2;
    const int qc = (lid & 3) * 2;
    const int m0 = mt * BM + wm * 32;

    #pragma unroll 1
    for (int nb = 0; nb < NDIM / BN; nb++) {
        // previous iteration's smem B readers must be done before overwrite;
        // first iteration: also publishes the A image.
        __syncthreads();
        {
            const uint4* sw = reinterpret_cast<const uint4*>(g_wq + nb * 65536u);
            uint4* db = reinterpret_cast<uint4*>(smem + SMEM_B_OFF);
            #pragma unroll
            for (int i = 0; i < 16; i++)
                db[tid + i * GEMM_THREADS] = sw[tid + i * GEMM_THREADS];
        }
        __syncthreads();

        float acc[2][4][4];
        #pragma unroll
        for (int i = 0; i < 2; i++)
            #pragma unroll
            for (int j = 0; j < 4; j++)
                #pragma unroll
                for (int c = 0; c < 4; c++) acc[i][j][c] = 0.0f;

        // mainloop: 16 K-steps of 32
        #pragma unroll
        for (int ks = 0; ks < 16; ks++) {
            uint32_t a0[4], a1[4], b0[4], b1[4];
            uint32_t ga = ((uint32_t)(ks * 2) + ahalf) ^ lxor;
            uint32_t gb = ((uint32_t)(ks * 2) + bhalf) ^ lxor;
            ldsm_x4(a0, abase + (ga << 4));
            ldsm_x4(a1, abase + 16u * 512u + (ga << 4));
            ldsm_x4(b0, bbase + (gb << 4));
            ldsm_x4(b1, bbase + 16u * 512u + (gb << 4));
            mma_e4m3(acc[0][0], a0, b0[0], b0[1]);
            mma_e4m3(acc[0][1], a0, b0[2], b0[3]);
            mma_e4m3(acc[0][2], a0, b1[0], b1[1]);
            mma_e4m3(acc[0][3], a0, b1[2], b1[3]);
            mma_e4m3(acc[1][0], a1, b0[0], b0[1]);
            mma_e4m3(acc[1][1], a1, b0[2], b0[3]);
            mma_e4m3(acc[1][2], a1, b1[0], b1[1]);
            mma_e4m3(acc[1][3], a1, b1[2], b1[3]);
        }

        // epilogue: dequant + float2 stores
        const int n0 = nb * BN + wn * 32;
        #pragma unroll
        for (int tm = 0; tm < 2; tm++) {
            #pragma unroll
            for (int tn = 0; tn < 4; tn++) {
                const float* c = acc[tm][tn];
                size_t r0 = (size_t)(m0 + tm * 16 + qr) * NDIM + n0 + tn * 8 + qc;
                *reinterpret_cast<float2*>(out + r0) =
                    make_float2(c[0] * inv, c[1] * inv);
                *reinterpret_cast<float2*>(out + r0 + (size_t)8 * NDIM) =
                    make_float2(c[2] * inv, c[3] * inv);
            }
        }
    }
}

// ---------------------------------------------------------------------------
// launch: 4 kernels
// ---------------------------------------------------------------------------
extern "C" void kernel_launch(void* const* d_in, const int* in_sizes, int n_in,
                              void* d_out, int out_size) {
    const float* x = (const float*)d_in[0];
    const float* w = (const float*)d_in[1];
    float* out = (float*)d_out;

    init_kernel<<<1, 1>>>();
    amax_all_kernel<<<X_AMAX_BLOCKS + W_AMAX_BLOCKS, 256>>>(
        (const float4*)x, (const float4*)w);
    quant_w_kernel<<<512, 512>>>(w);

    cudaFuncSetAttribute(fp8_gemm_kernel,
                         cudaFuncAttributeMaxDynamicSharedMemorySize,
                         SMEM_TOTAL);
    fp8_gemm_kernel<<<MDIM / BM, GEMM_THREADS, SMEM_TOTAL>>>(x, out);
}

// round 7
// speedup vs baseline: 1.4044x; 1.4044x over previous
#include <cuda_runtime.h>
#include <cstdint>

// ============================================================================
// out = dequant( fp8(x*xs) @ fp8(w^T*ws)^T ) * (1/xs)(1/ws)
//   x: [8,8192,512] f32 -> M=65536, K=512 ; w: [512,512] f32 -> N=512
// 4 launches: init / amax(x,w) / quant_w / fused quant-A + FP8 GEMM.
// GEMM: CTA = 64(M) x 128(N) x fullK, 4 warps, warp tile 32x64,
// 2 CTAs/SM, reg-rich (256/thread), zero-ALU swizzled LDSM addressing,
// 1-step fragment prefetch. mma.sync m16n8k32 e4m3 (tcgen05 unusable:
// harness lowers via plain compute_103 PTX which rejects 'a'-gated instrs).
// ============================================================================

#define KDIM 512
#define NDIM 512
#define MDIM 65536
#define BM 64
#define BN 128
#define GEMM_THREADS 128
#define X_AMAX_BLOCKS 2048
#define W_AMAX_BLOCKS 8

#define SMEM_A_OFF 0
#define SMEM_A_BYTES (BM * KDIM)                  // 32768
#define SMEM_B_OFF SMEM_A_BYTES
#define SMEM_B_BYTES (BN * KDIM)                  // 65536
#define SMEM_TOTAL (SMEM_A_BYTES + SMEM_B_BYTES)  // 98304

// ---------------------------------------------------------------------------
// device globals
// ---------------------------------------------------------------------------
__device__ unsigned int g_amax_x_bits;
__device__ unsigned int g_amax_w_bits;
// B image: per n-block (128 rows): offset = nb*65536 + r*512 + swz(g,r), r=n%128
__device__ unsigned char g_wq[NDIM * KDIM];

// ---------------------------------------------------------------------------
// helpers
// ---------------------------------------------------------------------------
__device__ __forceinline__ uint32_t smem_u32(const void* p) {
    uint32_t a;
    asm("{ .reg .u64 t; cvta.to.shared.u64 t, %1; cvt.u32.u64 %0, t; }"
        : "=r"(a) : "l"(p));
    return a;
}

// 16B-granule swizzle within a 512B row: granule g of row r -> ((g^(r&7))<<4)
__device__ __forceinline__ uint32_t swz(uint32_t g, uint32_t r) {
    return (g ^ (r & 7u)) << 4;
}

// IEEE-exact scales (identical formula in every consumer kernel)
__device__ __forceinline__ float x_scale_inline() {
    return __fdiv_rn(448.0f, fmaxf(__uint_as_float(g_amax_x_bits), 1e-12f));
}
__device__ __forceinline__ float w_scale_inline() {
    return __fdiv_rn(448.0f, fmaxf(__uint_as_float(g_amax_w_bits), 1e-12f));
}

// pack two floats -> two e4m3 bytes (RN + saturate == reference clip+cast)
__device__ __forceinline__ uint32_t f2e4m3x2(float lo, float hi) {
    unsigned short v;
    asm("cvt.rn.satfinite.e4m3x2.f32 %0, %1, %2;" : "=h"(v) : "f"(hi), "f"(lo));
    return (uint32_t)v;
}

__device__ __forceinline__ unsigned char f2e4m3_one(float f) {
    unsigned short v;
    asm("cvt.rn.satfinite.e4m3x2.f32 %0, %1, %2;" : "=h"(v) : "f"(0.0f), "f"(f));
    return (unsigned char)(v & 0xFF);
}

__device__ __forceinline__ void ldsm_x4(uint32_t* r, uint32_t addr) {
    asm volatile(
        "ldmatrix.sync.aligned.m8n8.x4.shared.b16 {%0,%1,%2,%3}, [%4];"
        : "=r"(r[0]), "=r"(r[1]), "=r"(r[2]), "=r"(r[3]) : "r"(addr));
}

__device__ __forceinline__ void mma_e4m3(float* d, const uint32_t* a,
                                         uint32_t b0, uint32_t b1) {
    asm volatile(
        "mma.sync.aligned.m16n8k32.row.col.f32.e4m3.e4m3.f32 "
        "{%0,%1,%2,%3}, {%4,%5,%6,%7}, {%8,%9}, {%0,%1,%2,%3};"
        : "+f"(d[0]), "+f"(d[1]), "+f"(d[2]), "+f"(d[3])
        : "r"(a[0]), "r"(a[1]), "r"(a[2]), "r"(a[3]), "r"(b0), "r"(b1));
}

// ---------------------------------------------------------------------------
// kernel 1: reset amax accumulators
// ---------------------------------------------------------------------------
__global__ void init_kernel() {
    g_amax_x_bits = 0u;
    g_amax_w_bits = 0u;
}

// ---------------------------------------------------------------------------
// kernel 2: fused grid-stride |max| over x and w (bit-max == float-max >= 0)
// ---------------------------------------------------------------------------
__global__ void amax_all_kernel(const float4* __restrict__ x4,
                                const float4* __restrict__ w4) {
    const bool is_w = blockIdx.x >= X_AMAX_BLOCKS;
    const float4* p = is_w ? w4 : x4;
    const int n4 = is_w ? (KDIM * NDIM) / 4 : (MDIM * KDIM) / 4;
    const int bid = is_w ? (blockIdx.x - X_AMAX_BLOCKS) : blockIdx.x;
    const int nblk = is_w ? W_AMAX_BLOCKS : X_AMAX_BLOCKS;

    float m = 0.0f;
    for (int i = bid * blockDim.x + threadIdx.x; i < n4; i += nblk * blockDim.x) {
        float4 v = p[i];
        m = fmaxf(m, fmaxf(fmaxf(fabsf(v.x), fabsf(v.y)),
                           fmaxf(fabsf(v.z), fabsf(v.w))));
    }
    #pragma unroll
    for (int o = 16; o; o >>= 1) m = fmaxf(m, __shfl_xor_sync(0xffffffffu, m, o));
    __shared__ float wmax[8];
    int wid = threadIdx.x >> 5;
    if ((threadIdx.x & 31) == 0) wmax[wid] = m;
    __syncthreads();
    if (threadIdx.x < 8) {
        float mm = wmax[threadIdx.x];
        #pragma unroll
        for (int o = 4; o; o >>= 1) mm = fmaxf(mm, __shfl_xor_sync(0xffu, mm, o));
        if (threadIdx.x == 0) {
            atomicMax(is_w ? &g_amax_w_bits : &g_amax_x_bits,
                      __float_as_uint(mm));
        }
    }
}

// ---------------------------------------------------------------------------
// kernel 3: quantize weight transposed into pre-swizzled B SMEM images
// ---------------------------------------------------------------------------
__global__ void quant_w_kernel(const float* __restrict__ w) {
    int idx = blockIdx.x * blockDim.x + threadIdx.x;  // k*512 + n
    float ws = w_scale_inline();
    int k = idx >> 9;
    int n = idx & 511;
    unsigned char b = f2e4m3_one(w[idx] * ws);
    uint32_t r = (uint32_t)(n & 127);
    uint32_t off = (uint32_t)(n >> 7) * 65536u + r * 512u +
                   swz((uint32_t)k >> 4, r) + (uint32_t)(k & 15);
    g_wq[off] = b;
}

// ---------------------------------------------------------------------------
// GEMM fragment loader: 2 A ldsm.x4 + 4 B ldsm.x4 for one K-step of 32.
// All addresses are [precomputed_reg + compile-time imm] (zero inner ALU).
// ---------------------------------------------------------------------------
__device__ __forceinline__ void load_frags(uint32_t* a, uint32_t* b,
                                           const uint32_t* aaddr,
                                           const uint32_t* baddr, int ks) {
    const uint32_t off = (uint32_t)(ks >> 2) * 128u;  // folds into imm when unrolled
    ldsm_x4(a + 0, aaddr[ks & 3] + off);           // m rows +0..15
    ldsm_x4(a + 4, aaddr[ks & 3] + off + 8192u);   // m rows +16..31
    ldsm_x4(b + 0,  baddr[ks & 3] + off);          // n rows +0..15
    ldsm_x4(b + 4,  baddr[ks & 3] + off + 8192u);  // n rows +16..31
    ldsm_x4(b + 8,  baddr[ks & 3] + off + 16384u); // n rows +32..47
    ldsm_x4(b + 12, baddr[ks & 3] + off + 24576u); // n rows +48..63
}

// ---------------------------------------------------------------------------
// kernel 4: fused quantize-A + FP8 GEMM.
// CTA: 64x128, 4 warps (warp tile 32x64), full K=512 in SMEM, nb loop over 4
// B tiles (64KB each, L2-resident). 2 CTAs/SM.
// ---------------------------------------------------------------------------
__global__ void __launch_bounds__(GEMM_THREADS, 2)
fp8_gemm_kernel(const float* __restrict__ x, float* __restrict__ out) {
    extern __shared__ char smem[];
    const uint32_t sb = smem_u32(smem);
    const int tid = threadIdx.x;
    const int lid = tid & 31;
    const int wid = tid >> 5;
    const int wm = wid & 1;   // m-subtile of 32
    const int wn = wid >> 1;  // n-subtile of 64
    const int mt = blockIdx.x;

    // ---- quantize this CTA's A slice: 64 rows x 512 -> swizzled smem image
    const float xs = x_scale_inline();
    #pragma unroll
    for (int i = 0; i < 16; i++) {
        int g = tid + i * GEMM_THREADS;  // granule id, 0..2047
        int r = g >> 5;
        int gc = g & 31;
        const float4* p = reinterpret_cast<const float4*>(
            x + (size_t)(mt * BM + r) * KDIM + gc * 16);
        float4 f0 = p[0], f1 = p[1], f2 = p[2], f3 = p[3];
        uint4 q;
        q.x = f2e4m3x2(f0.x * xs, f0.y * xs) | (f2e4m3x2(f0.z * xs, f0.w * xs) << 16);
        q.y = f2e4m3x2(f1.x * xs, f1.y * xs) | (f2e4m3x2(f1.z * xs, f1.w * xs) << 16);
        q.z = f2e4m3x2(f2.x * xs, f2.y * xs) | (f2e4m3x2(f2.z * xs, f2.w * xs) << 16);
        q.w = f2e4m3x2(f3.x * xs, f3.y * xs) | (f2e4m3x2(f3.z * xs, f3.w * xs) << 16);
        *reinterpret_cast<uint4*>(smem + SMEM_A_OFF + r * 512 +
                                  swz((uint32_t)gc, (uint32_t)r)) = q;
    }

    // ---- precomputed LDSM base addresses.
    // granule(ks) = (2*ks + half) ^ (lid&7); since XOR touches only bits 0-2
    // of the granule index: addr(ks) = base[ks&3] + (ks>>2)*128.
    const uint32_t l = (uint32_t)(lid & 7);
    const uint32_t arow = (uint32_t)(wm * 32 + (lid & 15));
    const uint32_t ah = (uint32_t)(lid >> 4);
    const uint32_t brow = (uint32_t)(wn * 64 + (lid & 7) + ((lid & 16) >> 1));
    const uint32_t bh = (uint32_t)((lid >> 3) & 1);
    uint32_t aaddr[4], baddr[4];
    #pragma unroll
    for (uint32_t p4 = 0; p4 < 4; p4++) {
        aaddr[p4] = sb + SMEM_A_OFF + arow * 512u + (((2u * p4 + ah) ^ l) << 4);
        baddr[p4] = sb + SMEM_B_OFF + brow * 512u + (((2u * p4 + bh) ^ l) << 4);
    }

    const float ws = w_scale_inline();
    const float inv = __fmul_rn(__frcp_rn(xs), __frcp_rn(ws));
    const int qr = lid >> 2;
    const int qc = (lid & 3) * 2;
    const int m0 = mt * BM + wm * 32;

    #pragma unroll 1
    for (int nb = 0; nb < NDIM / BN; nb++) {
        __syncthreads();  // prior readers of smem B done (also publishes A once)
        {
            const uint4* sw = reinterpret_cast<const uint4*>(g_wq + nb * 65536u);
            uint4* db = reinterpret_cast<uint4*>(smem + SMEM_B_OFF);
            #pragma unroll
            for (int i = 0; i < 32; i++)
                db[tid + i * GEMM_THREADS] = sw[tid + i * GEMM_THREADS];
        }
        __syncthreads();

        float acc[2][8][4];
        #pragma unroll
        for (int i = 0; i < 2; i++)
            #pragma unroll
            for (int j = 0; j < 8; j++)
                #pragma unroll
                for (int c = 0; c < 4; c++) acc[i][j][c] = 0.0f;

        // mainloop: 16 K-steps of 32, fragment ping-pong prefetch
        uint32_t af[2][8], bf[2][16];
        load_frags(af[0], bf[0], aaddr, baddr, 0);
        #pragma unroll
        for (int ks = 0; ks < 16; ks++) {
            const int cur = ks & 1;
            if (ks < 15) load_frags(af[cur ^ 1], bf[cur ^ 1], aaddr, baddr, ks + 1);
            #pragma unroll
            for (int tm = 0; tm < 2; tm++) {
                #pragma unroll
                for (int tn = 0; tn < 8; tn++) {
                    mma_e4m3(acc[tm][tn], af[cur] + tm * 4,
                             bf[cur][tn * 2], bf[cur][tn * 2 + 1]);
                }
            }
        }

        // epilogue: dequant + float2 stores
        const int n0 = nb * BN + wn * 64;
        #pragma unroll
        for (int tm = 0; tm < 2; tm++) {
            #pragma unroll
            for (int tn = 0; tn < 8; tn++) {
                const float* c = acc[tm][tn];
                size_t r0 = (size_t)(m0 + tm * 16 + qr) * NDIM + n0 + tn * 8 + qc;
                *reinterpret_cast<float2*>(out + r0) =
                    make_float2(c[0] * inv, c[1] * inv);
                *reinterpret_cast<float2*>(out + r0 + (size_t)8 * NDIM) =
                    make_float2(c[2] * inv, c[3] * inv);
            }
        }
    }
}

// ---------------------------------------------------------------------------
// launch: 4 kernels
// ---------------------------------------------------------------------------
extern "C" void kernel_launch(void* const* d_in, const int* in_sizes, int n_in,
                              void* d_out, int out_size) {
    const float* x = (const float*)d_in[0];
    const float* w = (const float*)d_in[1];
    float* out = (float*)d_out;

    init_kernel<<<1, 1>>>();
    amax_all_kernel<<<X_AMAX_BLOCKS + W_AMAX_BLOCKS, 256>>>(
        (const float4*)x, (const float4*)w);
    quant_w_kernel<<<512, 512>>>(w);

    cudaFuncSetAttribute(fp8_gemm_kernel,
                         cudaFuncAttributeMaxDynamicSharedMemorySize,
                         SMEM_TOTAL);
    fp8_gemm_kernel<<<MDIM / BM, GEMM_THREADS, SMEM_TOTAL>>>(x, out);
}